// round 15
// baseline (speedup 1.0000x reference)
#include <cuda_runtime.h>
#include <cuda_fp16.h>
#include <cstdint>

#define B_    4
#define T_    4096
#define D_    1024
#define H_    16
#define DH_   64
#define NS_   4
#define CTX_  516
#define Q0_   3580
#define MTOT_ (B_*CTX_)   // 2064
#define XR_   520         // per-batch gathered x rows: 4 sinks + 516 window

// ---------------------------------------------------------------------------
// Device scratch (no allocation allowed). A-side operands: fp16 hi only.
// B-side operands (weights, K, V): fp16 hi+lo.
// ---------------------------------------------------------------------------
__device__ __align__(16) __half g_Xh[B_*XR_*D_];
__device__ __align__(16) __half g_Wth[4*D_*D_];   // W^T hi: [z][n][k]
__device__ __align__(16) __half g_Wtl[4*D_*D_];   // W^T lo
__device__ __align__(16) __half g_Qh[MTOT_*D_];   // Q (pre-scaled by 0.125)
__device__ __align__(16) __half g_Kh[MTOT_*D_];
__device__ __align__(16) __half g_Kl[MTOT_*D_];
__device__ __align__(16) __half g_Vh[MTOT_*D_];
__device__ __align__(16) __half g_Vl[MTOT_*D_];
__device__ __align__(16) __half g_AOh[MTOT_*D_];

// ---------------------------------------------------------------------------
__device__ __forceinline__ uint32_t smem_u32(const void* p) {
    uint32_t a;
    asm("{ .reg .u64 t; cvta.to.shared.u64 t, %1; cvt.u32.u64 %0, t; }" : "=r"(a) : "l"(p));
    return a;
}
// pack two fp32 -> half2 (a in low, b in high)
__device__ __forceinline__ uint32_t pack_hf2(float a, float b) {
    uint32_t r;
    asm("cvt.rn.f16x2.f32 %0, %1, %2;" : "=r"(r) : "f"(b), "f"(a));
    return r;
}
__device__ __forceinline__ void ldsm4(uint32_t* r, uint32_t addr) {
    asm volatile("ldmatrix.sync.aligned.m8n8.x4.shared.b16 {%0,%1,%2,%3}, [%4];"
        : "=r"(r[0]), "=r"(r[1]), "=r"(r[2]), "=r"(r[3]) : "r"(addr));
}
__device__ __forceinline__ void ldsm4t(uint32_t* r, uint32_t addr) {
    asm volatile("ldmatrix.sync.aligned.m8n8.x4.trans.shared.b16 {%0,%1,%2,%3}, [%4];"
        : "=r"(r[0]), "=r"(r[1]), "=r"(r[2]), "=r"(r[3]) : "r"(addr));
}
__device__ __forceinline__ void mma16816(float* c, const uint32_t* a, const uint32_t* b) {
    asm volatile(
        "mma.sync.aligned.m16n8k16.row.col.f32.f16.f16.f32 "
        "{%0,%1,%2,%3}, {%4,%5,%6,%7}, {%8,%9}, {%0,%1,%2,%3};"
        : "+f"(c[0]), "+f"(c[1]), "+f"(c[2]), "+f"(c[3])
        : "r"(a[0]), "r"(a[1]), "r"(a[2]), "r"(a[3]), "r"(b[0]), "r"(b[1]));
}
__device__ __forceinline__ void cpa16(uint32_t dst, const void* src, bool valid) {
    int sz = valid ? 16 : 0;
    asm volatile("cp.async.cg.shared.global [%0], [%1], 16, %2;"
        :: "r"(dst), "l"(src), "r"(sz) : "memory");
}
#define CPA_COMMIT() asm volatile("cp.async.commit_group;" ::: "memory")
#define CPA_WAIT(n)  asm volatile("cp.async.wait_group %0;" :: "n"(n) : "memory")

// ---------------------------------------------------------------------------
// prep_x: gather live x rows -> fp16 (hi only); zero-fill dead output rows.
// ---------------------------------------------------------------------------
__global__ __launch_bounds__(256) void prep_x(const float* __restrict__ x,
                                              float* __restrict__ out) {
    int gr = blockIdx.x;
    int b = gr / XR_, r = gr % XR_;
    int tok = (r < NS_) ? r : (Q0_ + (r - NS_));
    int t = threadIdx.x;
    float4 v = *(const float4*)(x + (size_t)(b * T_ + tok) * D_ + t * 4);
    uint2 hw = make_uint2(pack_hf2(v.x, v.y), pack_hf2(v.z, v.w));
    ((uint2*)g_Xh)[(size_t)gr * 256 + t] = hw;

    const size_t nz4 = (size_t)B_ * Q0_ * D_ / 4;
    const size_t stride = (size_t)B_ * XR_ * 256;
    const size_t perb = (size_t)Q0_ * D_;
    for (size_t i = (size_t)gr * 256 + t; i < nz4; i += stride) {
        size_t e = i * 4;
        size_t bb = e / perb, rr = e % perb;
        *(float4*)(out + bb * (size_t)T_ * D_ + rr) = make_float4(0.f, 0.f, 0.f, 0.f);
    }
}

// ---------------------------------------------------------------------------
// prep_w: transpose W (4 matrices) -> [n][k] fp16 hi/lo
// ---------------------------------------------------------------------------
__global__ __launch_bounds__(256) void prep_w(
    const float* __restrict__ Wq, const float* __restrict__ Wk,
    const float* __restrict__ Wv, const float* __restrict__ Wo)
{
    const int z = blockIdx.z;
    const float* __restrict__ W = (z == 0) ? Wq : (z == 1) ? Wk : (z == 2) ? Wv : Wo;
    __shared__ float tile[64][33];
    const int n0 = blockIdx.x * 32, k0 = blockIdx.y * 64;
    const int tx = threadIdx.x, ty = threadIdx.y;

    #pragma unroll
    for (int rr = 0; rr < 8; rr++) {
        int kk = ty + rr * 8;
        tile[kk][tx] = W[(size_t)(k0 + kk) * D_ + n0 + tx];
    }
    __syncthreads();
    #pragma unroll
    for (int rr = 0; rr < 4; rr++) {
        int n = ty + rr * 8;
        float v0 = tile[tx * 2][n], v1 = tile[tx * 2 + 1][n];
        float h0 = __half2float(__float2half_rn(v0));
        float h1 = __half2float(__float2half_rn(v1));
        size_t base = (size_t)z * D_ * D_ + (size_t)(n0 + n) * D_ + k0;
        ((uint32_t*)(g_Wth + base))[tx] = pack_hf2(v0, v1);
        ((uint32_t*)(g_Wtl + base))[tx] = pack_hf2(v0 - h0, v1 - h1);
    }
}

// ---------------------------------------------------------------------------
// Tensor-core GEMM: C = Ah*(Bh+Bl), fp16, 2 MMA passes.
// 3-stage cp.async pipeline, ONE barrier per chunk.
// modes 0/1/2 -> Q(hi) / K(hi+lo) / V(hi+lo); mode 3 -> final out (fp32).
// ---------------------------------------------------------------------------
#define GM 128
#define GN 128
#define KC 32
#define SPAD 40
#define NCHUNK (D_/KC)
#define STG  (GM*SPAD)
#define STGB (STG*2)
#define NSTAGE 3
#define GSMEM (3*NSTAGE*STG*2)        // 3 arrays x 3 stages = 92160 bytes

__global__ __launch_bounds__(256, 2) void gemm_mma(int mode_base, float* __restrict__ outF) {
    extern __shared__ __half ds[];
    __half* sAh = ds;
    __half* sBh = ds + NSTAGE * STG;
    __half* sBl = ds + 2 * NSTAGE * STG;

    const int mode = mode_base + blockIdx.z;
    const int n0 = blockIdx.x * GN;
    const int m0 = blockIdx.y * GM;
    const int tid = threadIdx.x;
    const int wid = tid >> 5, lane = tid & 31;
    const int warp_m = (wid & 1) * 64;
    const int warp_n = (wid >> 1) * 32;

    const __half* __restrict__ Bh_g = g_Wth + (size_t)mode * D_ * D_;
    const __half* __restrict__ Bl_g = g_Wtl + (size_t)mode * D_ * D_;
    const __half* __restrict__ Ah_g = (mode < 3) ? g_Xh : g_AOh;

    const int ar0 = tid >> 2, ar1 = ar0 + 64;
    const int q = tid & 3;
    long asrc0 = -1, asrc1 = -1;
    {
        int m = m0 + ar0;
        if (m < MTOT_) {
            if (mode < 3) { int b = m / CTX_, i = m % CTX_; asrc0 = (long)b * XR_ + ((mode == 0) ? (NS_ + i) : ((i < NS_) ? i : (NS_ + i))); }
            else asrc0 = m;
        }
        m = m0 + ar1;
        if (m < MTOT_) {
            if (mode < 3) { int b = m / CTX_, i = m % CTX_; asrc1 = (long)b * XR_ + ((mode == 0) ? (NS_ + i) : ((i < NS_) ? i : (NS_ + i))); }
            else asrc1 = m;
        }
    }
    const int so0 = ar0 * SPAD + q * 8;
    const int so1 = ar1 * SPAD + q * 8;
    const uint32_t dAh0 = smem_u32(sAh + so0), dAh1 = smem_u32(sAh + so1);
    const uint32_t dBh0 = smem_u32(sBh + so0), dBh1 = smem_u32(sBh + so1);
    const uint32_t dBl0 = smem_u32(sBl + so0), dBl1 = smem_u32(sBl + so1);

    const int a_row = (lane & 15), a_kh = (lane >> 4) << 3;
    uint32_t aAh[4];
    #pragma unroll
    for (int mt = 0; mt < 4; mt++) {
        int r = warp_m + mt * 16 + a_row;
        aAh[mt] = smem_u32(sAh + r * SPAD + a_kh);
    }
    const int b_row = (lane & 7) + ((lane >> 4) & 1) * 8;
    const int b_k   = ((lane >> 3) & 1) * 8;
    uint32_t bB01h, bB01l, bB23h, bB23l;
    {
        int r01 = warp_n + b_row, r23 = warp_n + 16 + b_row;
        bB01h = smem_u32(sBh + r01 * SPAD + b_k);
        bB01l = smem_u32(sBl + r01 * SPAD + b_k);
        bB23h = smem_u32(sBh + r23 * SPAD + b_k);
        bB23l = smem_u32(sBl + r23 * SPAD + b_k);
    }

    float acc[4][4][4];
    #pragma unroll
    for (int a = 0; a < 4; a++)
        #pragma unroll
        for (int b = 0; b < 4; b++)
            #pragma unroll
            for (int cc = 0; cc < 4; cc++) acc[a][b][cc] = 0.f;

    auto issue = [&](int c, int st) {
        const uint32_t so = (uint32_t)st * STGB;
        const size_t koff = (size_t)c * KC + q * 8;
        const size_t a0 = (asrc0 >= 0 ? (size_t)asrc0 : 0) * D_ + koff;
        const size_t a1 = (asrc1 >= 0 ? (size_t)asrc1 : 0) * D_ + koff;
        cpa16(dAh0 + so, Ah_g + a0, asrc0 >= 0);
        cpa16(dAh1 + so, Ah_g + a1, asrc1 >= 0);
        cpa16(dBh0 + so, Bh_g + (size_t)(n0 + ar0) * D_ + koff, true);
        cpa16(dBh1 + so, Bh_g + (size_t)(n0 + ar1) * D_ + koff, true);
        cpa16(dBl0 + so, Bl_g + (size_t)(n0 + ar0) * D_ + koff, true);
        cpa16(dBl1 + so, Bl_g + (size_t)(n0 + ar1) * D_ + koff, true);
        CPA_COMMIT();
    };

    issue(0, 0);
    issue(1, 1);
    int st = 0;           // stage of chunk c
    int st2 = 2;          // stage of chunk c+2
    for (int c = 0; c < NCHUNK; c++) {
        if (c + 1 < NCHUNK) { CPA_WAIT(1); } else { CPA_WAIT(0); }
        __syncthreads();   // all warps done with chunk c-1 (stage st2) -> safe to refill
        if (c + 2 < NCHUNK) issue(c + 2, st2);
        const uint32_t so = (uint32_t)st * STGB;
        #pragma unroll
        for (int ks = 0; ks < KC * 2; ks += 32) {
            uint32_t fBh[4][2], fBl[4][2], t4[4];
            ldsm4(t4, bB01h + so + ks);
            fBh[0][0] = t4[0]; fBh[0][1] = t4[1]; fBh[1][0] = t4[2]; fBh[1][1] = t4[3];
            ldsm4(t4, bB23h + so + ks);
            fBh[2][0] = t4[0]; fBh[2][1] = t4[1]; fBh[3][0] = t4[2]; fBh[3][1] = t4[3];
            ldsm4(t4, bB01l + so + ks);
            fBl[0][0] = t4[0]; fBl[0][1] = t4[1]; fBl[1][0] = t4[2]; fBl[1][1] = t4[3];
            ldsm4(t4, bB23l + so + ks);
            fBl[2][0] = t4[0]; fBl[2][1] = t4[1]; fBl[3][0] = t4[2]; fBl[3][1] = t4[3];

            #pragma unroll
            for (int mp = 0; mp < 2; mp++) {
                const int mt0 = mp * 2, mt1 = mp * 2 + 1;
                uint32_t fA0[4], fA1[4];
                ldsm4(fA0, aAh[mt0] + so + ks);
                ldsm4(fA1, aAh[mt1] + so + ks);
                #pragma unroll
                for (int nt = 0; nt < 4; nt++) mma16816(acc[mt0][nt], fA0, fBh[nt]);
                #pragma unroll
                for (int nt = 0; nt < 4; nt++) mma16816(acc[mt1][nt], fA1, fBh[nt]);
                #pragma unroll
                for (int nt = 0; nt < 4; nt++) mma16816(acc[mt0][nt], fA0, fBl[nt]);
                #pragma unroll
                for (int nt = 0; nt < 4; nt++) mma16816(acc[mt1][nt], fA1, fBl[nt]);
            }
        }
        st  = (st  == NSTAGE - 1) ? 0 : st + 1;
        st2 = (st2 == NSTAGE - 1) ? 0 : st2 + 1;
    }

    const int er = lane >> 2, ec = (lane & 3) * 2;
    if (mode < 3) {
        __half* dh = (mode == 0) ? g_Qh : (mode == 1) ? g_Kh : g_Vh;
        __half* dl = (mode == 1) ? g_Kl : g_Vl;        // unused when mode==0
        const bool wlo = (mode != 0);
        const float scl = (mode == 0) ? 0.125f : 1.0f;
        #pragma unroll
        for (int mt = 0; mt < 4; mt++) {
            #pragma unroll
            for (int half = 0; half < 2; half++) {
                int mm = m0 + warp_m + mt * 16 + er + half * 8;
                if (mm < MTOT_) {
                    size_t base = (size_t)mm * D_ + n0 + warp_n + ec;
                    #pragma unroll
                    for (int nt = 0; nt < 4; nt++) {
                        float v0 = acc[mt][nt][half * 2] * scl;
                        float v1 = acc[mt][nt][half * 2 + 1] * scl;
                        *(uint32_t*)(dh + base + nt * 8) = pack_hf2(v0, v1);
                        if (wlo) {
                            float t0 = __half2float(__float2half_rn(v0));
                            float t1 = __half2float(__float2half_rn(v1));
                            *(uint32_t*)(dl + base + nt * 8) = pack_hf2(v0 - t0, v1 - t1);
                        }
                    }
                }
            }
        }
    } else {
        #pragma unroll
        for (int mt = 0; mt < 4; mt++) {
            #pragma unroll
            for (int half = 0; half < 2; half++) {
                int mm = m0 + warp_m + mt * 16 + er + half * 8;
                if (mm < MTOT_) {
                    int b = mm / CTX_, i = mm % CTX_;
                    float* dst = outF + (size_t)(b * T_ + Q0_ + i) * D_ + n0;
                    #pragma unroll
                    for (int nt = 0; nt < 4; nt++) {
                        float2 v = make_float2(acc[mt][nt][half * 2], acc[mt][nt][half * 2 + 1]);
                        *(float2*)(dst + warp_n + nt * 8 + ec) = v;
                    }
                }
            }
        }
    }
}

// ---------------------------------------------------------------------------
// Flash attention (fp16): S = Qh*(Kh+Kl), O += Ph*(Vh+Vl).
// cp.async double-buffered, tile-paired blocks, 128 threads. (R13, frozen)
// ---------------------------------------------------------------------------
#define SST   72
#define TILEH (64*SST)
#define NTILE ((CTX_ + 63) / 64)       // 9
#define TMAX  (NTILE - 1)              // 8
#define NPAIR ((NTILE + 1) / 2)        // 5
#define ASMEM (2 * 4 * TILEH * 2)      // 73728 bytes

__global__ __launch_bounds__(128) void attn_mma() {
    extern __shared__ __half as_[];
    const int b = blockIdx.z, h = blockIdx.y, p = blockIdx.x;
    const int tid = threadIdx.x, warp = tid >> 5, lane = tid & 31;

    const uint32_t sbase = smem_u32(as_);
    const __half* __restrict__ KVsrc[4] = { g_Kh, g_Kl, g_Vh, g_Vl };

    const int srow = tid >> 3;
    const int sdd  = (tid & 7) * 8;

    const uint32_t k4o = (uint32_t)((((lane & 7) + ((lane >> 4) & 1) * 8) * SST + ((lane >> 3) & 1) * 8) * 2);
    const uint32_t v4o = (uint32_t)((((lane & 7) + ((lane >> 3) & 1) * 8) * SST) * 2 + ((lane >> 4) & 1) * 16);
    const uint32_t qfo = (uint32_t)((warp * 16 + (lane & 15)) * (SST * 2) + ((lane >> 4) & 1) * 16);

    const int npass = (2 * p == TMAX) ? 1 : 2;
    for (int pass = 0; pass < npass; pass++) {
        const int tau = (pass == 0) ? p : (TMAX - p);
        const int gq0 = tau * 64 + warp * 16 + (lane >> 2);
        const int gq1 = gq0 + 8;

        const uint4 zv = make_uint4(0, 0, 0, 0);
        for (int it = tid; it < 64 * 8; it += 128) {
            int row = it >> 3, dd = (it & 7) * 8;
            int gq = tau * 64 + row;
            uint4 vh = zv;
            if (gq < CTX_) {
                size_t off = (size_t)(b * CTX_ + gq) * D_ + h * DH_ + dd;
                vh = *(const uint4*)(g_Qh + off);
            }
            *(uint4*)(as_ + row * SST + dd) = vh;
        }
        __syncthreads();
        uint32_t QhF[4][4];
        #pragma unroll
        for (int ks = 0; ks < 4; ks++)
            ldsm4(QhF[ks], sbase + qfo + ks * 32);
        __syncthreads();

        float oacc[8][4];
        #pragma unroll
        for (int nt = 0; nt < 8; nt++)
            #pragma unroll
            for (int c = 0; c < 4; c++) oacc[nt][c] = 0.f;
        float m0 = -1e30f, m1 = -1e30f, l0 = 0.f, l1 = 0.f;

        auto issueTile = [&](int t, int s) {
            #pragma unroll
            for (int rr = 0; rr < 4; rr++) {
                int row = srow + rr * 16;
                int j = t * 64 + row;
                bool v = (j < CTX_);
                size_t off = (size_t)(b * CTX_ + (v ? j : 0)) * D_ + h * DH_ + sdd;
                uint32_t dst = sbase + (uint32_t)(((s * 4) * TILEH + row * SST + sdd) * 2);
                #pragma unroll
                for (int a = 0; a < 4; a++)
                    cpa16(dst + (uint32_t)(a * TILEH * 2), KVsrc[a] + off, v);
            }
            CPA_COMMIT();
        };

        issueTile(0, 0);
        for (int t = 0; t <= tau; t++) {
            if (t + 1 <= tau) { issueTile(t + 1, (t + 1) & 1); CPA_WAIT(1); }
            else              { CPA_WAIT(0); }
            __syncthreads();
            const uint32_t sb = sbase + (uint32_t)((t & 1) * 4 * TILEH * 2);
            const uint32_t kbh = sb + 0 * TILEH * 2 + k4o;
            const uint32_t kbl = sb + 1 * TILEH * 2 + k4o;
            const uint32_t vbh = sb + 2 * TILEH * 2 + v4o;
            const uint32_t vbl = sb + 3 * TILEH * 2 + v4o;

            float sacc[8][4];
            #pragma unroll
            for (int nt = 0; nt < 8; nt++)
                #pragma unroll
                for (int c = 0; c < 4; c++) sacc[nt][c] = 0.f;

            #pragma unroll
            for (int ks = 0; ks < 4; ks++) {
                #pragma unroll
                for (int pp = 0; pp < 4; pp++) {
                    uint32_t th[4], tl[4];
                    ldsm4(th, kbh + (uint32_t)(pp * 16 * SST * 2 + ks * 32));
                    ldsm4(tl, kbl + (uint32_t)(pp * 16 * SST * 2 + ks * 32));
                    mma16816(sacc[2 * pp + 0], QhF[ks], th);
                    mma16816(sacc[2 * pp + 1], QhF[ks], th + 2);
                    mma16816(sacc[2 * pp + 0], QhF[ks], tl);
                    mma16816(sacc[2 * pp + 1], QhF[ks], tl + 2);
                }
            }

            if (t == tau) {
                const int cbase = t * 64 + 2 * (lane & 3);
                #pragma unroll
                for (int nt = 0; nt < 8; nt++) {
                    int c0 = cbase + nt * 8, c1 = c0 + 1;
                    if (c0 > gq0) sacc[nt][0] = -1e30f;
                    if (c1 > gq0) sacc[nt][1] = -1e30f;
                    if (c0 > gq1) sacc[nt][2] = -1e30f;
                    if (c1 > gq1) sacc[nt][3] = -1e30f;
                }
            }

            float mx0 = -1e30f, mx1 = -1e30f;
            #pragma unroll
            for (int nt = 0; nt < 8; nt++) {
                mx0 = fmaxf(mx0, fmaxf(sacc[nt][0], sacc[nt][1]));
                mx1 = fmaxf(mx1, fmaxf(sacc[nt][2], sacc[nt][3]));
            }
            mx0 = fmaxf(mx0, __shfl_xor_sync(0xFFFFFFFFu, mx0, 1));
            mx0 = fmaxf(mx0, __shfl_xor_sync(0xFFFFFFFFu, mx0, 2));
            mx1 = fmaxf(mx1, __shfl_xor_sync(0xFFFFFFFFu, mx1, 1));
            mx1 = fmaxf(mx1, __shfl_xor_sync(0xFFFFFFFFu, mx1, 2));
            float mn0 = fmaxf(m0, mx0), mn1 = fmaxf(m1, mx1);
            float al0 = __expf(m0 - mn0), al1 = __expf(m1 - mn1);
            m0 = mn0; m1 = mn1;

            float rs0 = 0.f, rs1 = 0.f;
            #pragma unroll
            for (int nt = 0; nt < 8; nt++) {
                float p00 = __expf(sacc[nt][0] - mn0);
                float p01 = __expf(sacc[nt][1] - mn0);
                float p10 = __expf(sacc[nt][2] - mn1);
                float p11 = __expf(sacc[nt][3] - mn1);
                sacc[nt][0] = p00; sacc[nt][1] = p01;
                sacc[nt][2] = p10; sacc[nt][3] = p11;
                rs0 += p00 + p01; rs1 += p10 + p11;
            }
            rs0 += __shfl_xor_sync(0xFFFFFFFFu, rs0, 1);
            rs0 += __shfl_xor_sync(0xFFFFFFFFu, rs0, 2);
            rs1 += __shfl_xor_sync(0xFFFFFFFFu, rs1, 1);
            rs1 += __shfl_xor_sync(0xFFFFFFFFu, rs1, 2);
            l0 = l0 * al0 + rs0;
            l1 = l1 * al1 + rs1;

            #pragma unroll
            for (int nt = 0; nt < 8; nt++) {
                oacc[nt][0] *= al0; oacc[nt][1] *= al0;
                oacc[nt][2] *= al1; oacc[nt][3] *= al1;
            }

            #pragma unroll
            for (int u = 0; u < 4; u++) {
                uint32_t Ph[4];
                #pragma unroll
                for (int half = 0; half < 2; half++) {
                    const float* pa = sacc[2 * u + half];
                    Ph[half * 2 + 0] = pack_hf2(pa[0], pa[1]);
                    Ph[half * 2 + 1] = pack_hf2(pa[2], pa[3]);
                }
                #pragma unroll
                for (int pp = 0; pp < 4; pp++) {
                    uint32_t tvh[4], tvl[4];
                    ldsm4t(tvh, vbh + (uint32_t)(u * 16 * SST * 2 + pp * 32));
                    ldsm4t(tvl, vbl + (uint32_t)(u * 16 * SST * 2 + pp * 32));
                    mma16816(oacc[2 * pp + 0], Ph, tvh);
                    mma16816(oacc[2 * pp + 1], Ph, tvh + 2);
                    mma16816(oacc[2 * pp + 0], Ph, tvl);
                    mma16816(oacc[2 * pp + 1], Ph, tvl + 2);
                }
            }
            __syncthreads();
        }

        const int ccol = 2 * (lane & 3);
        if (gq0 < CTX_) {
            float inv = 1.f / l0;
            size_t base = (size_t)(b * CTX_ + gq0) * D_ + h * DH_ + ccol;
            #pragma unroll
            for (int nt = 0; nt < 8; nt++)
                *(uint32_t*)(g_AOh + base + nt * 8) =
                    pack_hf2(oacc[nt][0] * inv, oacc[nt][1] * inv);
        }
        if (gq1 < CTX_) {
            float inv = 1.f / l1;
            size_t base = (size_t)(b * CTX_ + gq1) * D_ + h * DH_ + ccol;
            #pragma unroll
            for (int nt = 0; nt < 8; nt++)
                *(uint32_t*)(g_AOh + base + nt * 8) =
                    pack_hf2(oacc[nt][2] * inv, oacc[nt][3] * inv);
        }
        __syncthreads();
    }
}

// ---------------------------------------------------------------------------
extern "C" void kernel_launch(void* const* d_in, const int* in_sizes, int n_in,
                              void* d_out, int out_size) {
    const float* x  = (const float*)d_in[0];
    const float* Wq = (const float*)d_in[1];
    const float* Wk = (const float*)d_in[2];
    const float* Wv = (const float*)d_in[3];
    const float* Wo = (const float*)d_in[4];
    float* out = (float*)d_out;

    cudaFuncSetAttribute(gemm_mma, cudaFuncAttributeMaxDynamicSharedMemorySize, GSMEM);
    cudaFuncSetAttribute(attn_mma, cudaFuncAttributeMaxDynamicSharedMemorySize, ASMEM);

    // 1. Prep (gather x -> fp16, zero-fill dead rows) + weight transpose/split
    prep_x<<<B_ * XR_, 256>>>(x, out);
    prep_w<<<dim3(D_ / 32, D_ / 64, 4), dim3(32, 8)>>>(Wq, Wk, Wv, Wo);

    // 2. Q/K/V projections (Q pre-scaled by 0.125)
    gemm_mma<<<dim3(D_ / GN, (MTOT_ + GM - 1) / GM, 3), 256, GSMEM>>>(0, nullptr);

    // 3. Flash attention on tensor cores
    attn_mma<<<dim3(NPAIR, H_, B_), 128, ASMEM>>>();

    // 4. Output projection, scattered to live rows
    gemm_mma<<<dim3(D_ / GN, (MTOT_ + GM - 1) / GM, 1), 256, GSMEM>>>(3, out);
}